// round 4
// baseline (speedup 1.0000x reference)
#include <cuda_runtime.h>
#include <math.h>

// Problem constants (T=4096, NE=DA=2048)
#define TT 4096
#define CC 2048
#define CHUNK 64
#define NCHUNK (TT / CHUNK)

// ---------------- scratch (no cudaMalloc allowed) ----------------
__device__ float g_k[TT * CC];    // k, then ek = exp(k)
__device__ float g_v[TT * CC];    // v, then ekv = exp(k)*v
__device__ float g_r[TT * CC];    // r, then sr = sigmoid(r)
__device__ float g_a2[TT * CC];   // sr * wkv
__device__ float g_pp[NCHUNK * CC];
__device__ float g_pq[NCHUNK * CC];
__device__ float g_ip[NCHUNK * CC];
__device__ float g_iq[NCHUNK * CC];
__device__ float g_ew[CC];
__device__ float g_ewL[CC];
__device__ float g_eu[CC];

// ---------------- per-channel constants ----------------
__global__ void precompute_kernel(const float* __restrict__ tf,
                                  const float* __restrict__ td) {
    int c = blockIdx.x * blockDim.x + threadIdx.x;
    if (c < CC) {
        float w = expf(-expf(td[c]));   // e^w, decay factor per step
        g_ew[c] = w;
        float p = w;
#pragma unroll
        for (int i = 0; i < 6; i++) p = p * p;   // w^64
        g_ewL[c] = p;
        g_eu[c] = expf(tf[c]);
    }
}

// ---------------- SGEMM: C[M,N] = mix(A)[M,K] @ B[K,N], fp32 ----------------
// MIX: A-row is replaced on the fly by x[t]*tm + x[t-1]*(1-tm) (row 0 pads zero).
#define BM 128
#define BN 128
#define BK 8
#define TM 8
#define TN 8

template <bool MIX>
__global__ __launch_bounds__(256, 2) void sgemm_kernel(
    const float* __restrict__ A, const float* __restrict__ tm,
    const float* __restrict__ B, float* __restrict__ C,
    int M, int N, int K) {
    __shared__ float As[BK][BM];
    __shared__ float Bs[BK][BN];
    const int tid = threadIdx.x;
    const int bxn = blockIdx.x * BN;
    const int bym = blockIdx.y * BM;
    const int arow = tid >> 1;           // 0..127
    const int acol = (tid & 1) << 2;     // 0 or 4
    const int brow = tid >> 5;           // 0..7
    const int bcol = (tid & 31) << 2;    // 0..124
    const int ty = tid >> 4;             // 0..15
    const int tx = tid & 15;             // 0..15

    const int grow = bym + arow;
    const float* Arow = A + (long)grow * K;
    const float* Aprev = (grow > 0) ? (Arow - K) : A;  // never read when grow==0
    const float* Bp = B + (long)brow * N + bxn + bcol;

    float acc[TM][TN];
#pragma unroll
    for (int i = 0; i < TM; i++)
#pragma unroll
        for (int j = 0; j < TN; j++) acc[i][j] = 0.f;

    for (int k0 = 0; k0 < K; k0 += BK) {
        float4 av = *reinterpret_cast<const float4*>(Arow + k0 + acol);
        if (MIX) {
            float4 t4 = *reinterpret_cast<const float4*>(tm + k0 + acol);
            float4 pv = make_float4(0.f, 0.f, 0.f, 0.f);
            if (grow > 0)
                pv = *reinterpret_cast<const float4*>(Aprev + k0 + acol);
            // xk = xx + tm*(x - xx)
            av.x = fmaf(t4.x, av.x - pv.x, pv.x);
            av.y = fmaf(t4.y, av.y - pv.y, pv.y);
            av.z = fmaf(t4.z, av.z - pv.z, pv.z);
            av.w = fmaf(t4.w, av.w - pv.w, pv.w);
        }
        As[acol + 0][arow] = av.x;
        As[acol + 1][arow] = av.y;
        As[acol + 2][arow] = av.z;
        As[acol + 3][arow] = av.w;
        *reinterpret_cast<float4*>(&Bs[brow][bcol]) =
            *reinterpret_cast<const float4*>(Bp + (long)k0 * N);
        __syncthreads();
#pragma unroll
        for (int kk = 0; kk < BK; kk++) {
            float a[TM], b[TN];
#pragma unroll
            for (int i = 0; i < TM; i += 4)
                *reinterpret_cast<float4*>(&a[i]) =
                    *reinterpret_cast<const float4*>(&As[kk][ty * TM + i]);
#pragma unroll
            for (int j = 0; j < TN; j += 4)
                *reinterpret_cast<float4*>(&b[j]) =
                    *reinterpret_cast<const float4*>(&Bs[kk][tx * TN + j]);
#pragma unroll
            for (int i = 0; i < TM; i++)
#pragma unroll
                for (int j = 0; j < TN; j++)
                    acc[i][j] = fmaf(a[i], b[j], acc[i][j]);
        }
        __syncthreads();
    }
#pragma unroll
    for (int i = 0; i < TM; i++) {
        float* cp = C + (long)(bym + ty * TM + i) * N + bxn + tx * TN;
        *reinterpret_cast<float4*>(cp) =
            make_float4(acc[i][0], acc[i][1], acc[i][2], acc[i][3]);
        *reinterpret_cast<float4*>(cp + 4) =
            make_float4(acc[i][4], acc[i][5], acc[i][6], acc[i][7]);
    }
}

// ---------------- epilogue: ek, ekv, sigmoid(r), in place ----------------
__global__ void post_kernel(int n4) {
    int i = blockIdx.x * blockDim.x + threadIdx.x;
    if (i >= n4) return;
    float4 k4 = reinterpret_cast<float4*>(g_k)[i];
    float4 v4 = reinterpret_cast<float4*>(g_v)[i];
    float4 r4 = reinterpret_cast<float4*>(g_r)[i];
    float e;
    e = expf(k4.x); k4.x = e; v4.x *= e;
    e = expf(k4.y); k4.y = e; v4.y *= e;
    e = expf(k4.z); k4.z = e; v4.z *= e;
    e = expf(k4.w); k4.w = e; v4.w *= e;
    r4.x = 1.f / (1.f + expf(-r4.x));
    r4.y = 1.f / (1.f + expf(-r4.y));
    r4.z = 1.f / (1.f + expf(-r4.z));
    r4.w = 1.f / (1.f + expf(-r4.w));
    reinterpret_cast<float4*>(g_k)[i] = k4;
    reinterpret_cast<float4*>(g_v)[i] = v4;
    reinterpret_cast<float4*>(g_r)[i] = r4;
}

// ---------------- chunked linear-recurrence scan ----------------
// State (P,Q) in plain space: P = p*e^o, Q = q*e^o of the reference.
// y_t = (P + eu*ekv_t)/(Q + eu*ek_t);  P <- w*P + ekv_t;  Q <- w*Q + ek_t.

__global__ void scan1_kernel() {
    int c = blockIdx.y * blockDim.x + threadIdx.x;
    int ch = blockIdx.x;
    float w = g_ew[c];
    float P = 0.f, Q = 0.f;
    int idx = ch * CHUNK * CC + c;
#pragma unroll 8
    for (int i = 0; i < CHUNK; i++) {
        P = fmaf(w, P, g_v[idx]);
        Q = fmaf(w, Q, g_k[idx]);
        idx += CC;
    }
    g_pp[ch * CC + c] = P;
    g_pq[ch * CC + c] = Q;
}

__global__ void scan2_kernel() {
    int c = blockIdx.x * blockDim.x + threadIdx.x;
    float wl = g_ewL[c];
    float P = 0.f, Q = 0.f;
#pragma unroll
    for (int j = 0; j < NCHUNK; j++) {
        g_ip[j * CC + c] = P;
        g_iq[j * CC + c] = Q;
        P = fmaf(wl, P, g_pp[j * CC + c]);
        Q = fmaf(wl, Q, g_pq[j * CC + c]);
    }
}

__global__ void scan3_kernel() {
    int c = blockIdx.y * blockDim.x + threadIdx.x;
    int ch = blockIdx.x;
    float w = g_ew[c], eu = g_eu[c];
    float P = g_ip[ch * CC + c], Q = g_iq[ch * CC + c];
    int idx = ch * CHUNK * CC + c;
#pragma unroll 4
    for (int i = 0; i < CHUNK; i++) {
        float ek = g_k[idx];
        float ekv = g_v[idx];
        float num = fmaf(eu, ekv, P);
        float den = fmaf(eu, ek, Q);
        g_a2[idx] = g_r[idx] * __fdividef(num, den);
        P = fmaf(w, P, ekv);
        Q = fmaf(w, Q, ek);
        idx += CC;
    }
}

// ---------------- launch ----------------
extern "C" void kernel_launch(void* const* d_in, const int* in_sizes, int n_in,
                              void* d_out, int out_size) {
    const float* x   = (const float*)d_in[0];
    const float* tf  = (const float*)d_in[1];
    const float* td  = (const float*)d_in[2];
    const float* tmk = (const float*)d_in[3];
    const float* tmv = (const float*)d_in[4];
    const float* tmr = (const float*)d_in[5];
    const float* Wk  = (const float*)d_in[6];
    const float* Wv  = (const float*)d_in[7];
    const float* Wr  = (const float*)d_in[8];
    const float* Wo  = (const float*)d_in[9];
    float* out = (float*)d_out;

    float *pk, *pv, *pr, *pa2;
    cudaGetSymbolAddress((void**)&pk, g_k);
    cudaGetSymbolAddress((void**)&pv, g_v);
    cudaGetSymbolAddress((void**)&pr, g_r);
    cudaGetSymbolAddress((void**)&pa2, g_a2);

    precompute_kernel<<<(CC + 255) / 256, 256>>>(tf, td);

    dim3 gg(CC / BN, TT / BM);
    sgemm_kernel<true><<<gg, 256>>>(x, tmk, Wk, pk, TT, CC, CC);
    sgemm_kernel<true><<<gg, 256>>>(x, tmv, Wv, pv, TT, CC, CC);
    sgemm_kernel<true><<<gg, 256>>>(x, tmr, Wr, pr, TT, CC, CC);

    post_kernel<<<(TT * CC / 4 + 255) / 256, 256>>>(TT * CC / 4);

    scan1_kernel<<<dim3(NCHUNK, CC / 256), 256>>>();
    scan2_kernel<<<CC / 256, 256>>>();
    scan3_kernel<<<dim3(NCHUNK, CC / 256), 256>>>();

    sgemm_kernel<false><<<gg, 256>>>(pa2, nullptr, Wo, out, TT, CC, CC);
}

// round 10
// speedup vs baseline: 3.3930x; 3.3930x over previous
#include <cuda_runtime.h>
#include <cuda_bf16.h>
#include <math.h>
#include <stdint.h>

// Problem constants (T=4096, NE=DA=2048)
#define TT 4096
#define CC 2048
#define CHUNK 64
#define NCHUNK (TT / CHUNK)

// ---------------- scratch (no cudaMalloc allowed) ----------------
__device__ float g_k[TT * CC];    // k, then ek = exp(k)
__device__ float g_v[TT * CC];    // v, then ekv = exp(k)*v
__device__ float g_r[TT * CC];    // r, then sr = sigmoid(r)
// bf16 hi/lo splits of the three mixed activations [T, CC] (K-major)
__device__ __nv_bfloat16 g_akh[TT * CC], g_akl[TT * CC];
__device__ __nv_bfloat16 g_avh[TT * CC], g_avl[TT * CC];
__device__ __nv_bfloat16 g_arh[TT * CC], g_arl[TT * CC];
// bf16 hi/lo split of sr*wkv [T, CC]
__device__ __nv_bfloat16 g_a2h[TT * CC], g_a2l[TT * CC];
// transposed weight splits [N, K] bf16 (K-major rows)
__device__ __nv_bfloat16 g_wkh[CC * CC], g_wkl[CC * CC];
__device__ __nv_bfloat16 g_wvh[CC * CC], g_wvl[CC * CC];
__device__ __nv_bfloat16 g_wrh[CC * CC], g_wrl[CC * CC];
__device__ __nv_bfloat16 g_woh[CC * CC], g_wol[CC * CC];
// scan partials
__device__ float g_pp[NCHUNK * CC];
__device__ float g_pq[NCHUNK * CC];
__device__ float g_ip[NCHUNK * CC];
__device__ float g_iq[NCHUNK * CC];
__device__ float g_ew[CC];
__device__ float g_ewL[CC];
__device__ float g_eu[CC];

// ---------------- per-channel constants ----------------
__global__ void precompute_kernel(const float* __restrict__ tf,
                                  const float* __restrict__ td) {
    int c = blockIdx.x * blockDim.x + threadIdx.x;
    if (c < CC) {
        float w = expf(-expf(td[c]));   // e^w, decay factor per step
        g_ew[c] = w;
        float p = w;
#pragma unroll
        for (int i = 0; i < 6; i++) p = p * p;   // w^64
        g_ewL[c] = p;
        g_eu[c] = expf(tf[c]);
    }
}

// ---------------- weight transpose + bf16 split: W[K,N] -> H,L [N,K] ----------------
__global__ void wsplit_kernel(const float* __restrict__ W,
                              __nv_bfloat16* __restrict__ H,
                              __nv_bfloat16* __restrict__ L) {
    __shared__ float tile[32][33];
    int n0 = blockIdx.x * 32, k0 = blockIdx.y * 32;
    int tx = threadIdx.x, ty = threadIdx.y;  // 32 x 8
#pragma unroll
    for (int i = 0; i < 32; i += 8)
        tile[ty + i][tx] = W[(long)(k0 + ty + i) * CC + n0 + tx];
    __syncthreads();
#pragma unroll
    for (int i = 0; i < 32; i += 8) {
        float v = tile[tx][ty + i];  // = W[k0+tx][n0+ty+i]
        __nv_bfloat16 h = __float2bfloat16(v);
        long o = (long)(n0 + ty + i) * CC + k0 + tx;
        H[o] = h;
        L[o] = __float2bfloat16(v - __bfloat162float(h));
    }
}

// ---------------- activation mix + bf16 split ----------------
__global__ void asplit_kernel(const float* __restrict__ x,
                              const float* __restrict__ tmk,
                              const float* __restrict__ tmv,
                              const float* __restrict__ tmr) {
    int i = blockIdx.x * blockDim.x + threadIdx.x;
    if (i >= TT * CC) return;
    int c = i & (CC - 1);
    float xv = x[i];
    float xx = (i >= CC) ? x[i - CC] : 0.f;
    float d = xv - xx;
    float mk = fmaf(tmk[c], d, xx);
    float mv = fmaf(tmv[c], d, xx);
    float mr = fmaf(tmr[c], d, xx);
    __nv_bfloat16 h;
    h = __float2bfloat16(mk); g_akh[i] = h; g_akl[i] = __float2bfloat16(mk - __bfloat162float(h));
    h = __float2bfloat16(mv); g_avh[i] = h; g_avl[i] = __float2bfloat16(mv - __bfloat162float(h));
    h = __float2bfloat16(mr); g_arh[i] = h; g_arl[i] = __float2bfloat16(mr - __bfloat162float(h));
}

// ---------------- bf16x3-split GEMM via mma.sync (sm_80-class PTX only) ----------------
// C[M,N](fp32) = (Ah+Al)[M,K] @ (Bh+Bl)[N,K]^T, dropping Al*Bl.
#define GM 128
#define GN 128
#define GK 64
#define GNS (CC / GK)         // 32 K-stages
#define TILE_BYTES 16384      // 128 rows x 128B (bf16 x 64)
#define BUF_BYTES (4 * TILE_BYTES)
#define SMEM_DYN (2 * BUF_BYTES + 1024)

__device__ __forceinline__ uint32_t smem_u32(const void* p) {
    uint32_t a;
    asm("{ .reg .u64 t; cvta.to.shared.u64 t, %1; cvt.u32.u64 %0, t; }"
        : "=r"(a) : "l"(p));
    return a;
}
__device__ __forceinline__ void cp16(uint32_t dst, const void* src) {
    asm volatile("cp.async.cg.shared.global [%0], [%1], 16;" :: "r"(dst), "l"(src) : "memory");
}
__device__ __forceinline__ void ldsm4(uint32_t& r0, uint32_t& r1, uint32_t& r2,
                                      uint32_t& r3, uint32_t addr) {
    asm volatile("ldmatrix.sync.aligned.m8n8.x4.shared.b16 {%0,%1,%2,%3}, [%4];"
                 : "=r"(r0), "=r"(r1), "=r"(r2), "=r"(r3) : "r"(addr));
}
__device__ __forceinline__ void mma16816(float* c, uint32_t a0, uint32_t a1,
                                         uint32_t a2, uint32_t a3,
                                         uint32_t b0, uint32_t b1) {
    asm volatile(
        "mma.sync.aligned.m16n8k16.row.col.f32.bf16.bf16.f32 "
        "{%0,%1,%2,%3}, {%4,%5,%6,%7}, {%8,%9}, {%0,%1,%2,%3};"
        : "+f"(c[0]), "+f"(c[1]), "+f"(c[2]), "+f"(c[3])
        : "r"(a0), "r"(a1), "r"(a2), "r"(a3), "r"(b0), "r"(b1));
}

__device__ __forceinline__ void load_stage(
    uint32_t sb, const __nv_bfloat16* Ah, const __nv_bfloat16* Al,
    const __nv_bfloat16* Bh, const __nv_bfloat16* Bl,
    int m0, int n0, int s, int tid) {
    uint32_t base = sb + (uint32_t)(s & 1) * BUF_BYTES;
    int k0 = s * GK;
#pragma unroll
    for (int i = 0; i < 4; i++) {
        int c = tid + i * 256;          // 0..1023 chunk id
        int row = c >> 3;
        int colb = (c & 7) * 16;        // byte offset within 128B row
        uint32_t off = (uint32_t)(row * 128 + colb);
        uint32_t sw = off ^ ((off >> 3) & 0x70);
        const char* pa = (const char*)(Ah + (long)(m0 + row) * CC + k0) + colb;
        const char* pl = (const char*)(Al + (long)(m0 + row) * CC + k0) + colb;
        const char* pb = (const char*)(Bh + (long)(n0 + row) * CC + k0) + colb;
        const char* pm = (const char*)(Bl + (long)(n0 + row) * CC + k0) + colb;
        cp16(base + sw, pa);
        cp16(base + TILE_BYTES + sw, pl);
        cp16(base + 2 * TILE_BYTES + sw, pb);
        cp16(base + 3 * TILE_BYTES + sw, pm);
    }
    asm volatile("cp.async.commit_group;" ::: "memory");
}

__global__ __launch_bounds__(256, 1) void tc_gemm_kernel(
    const __nv_bfloat16* __restrict__ Ah, const __nv_bfloat16* __restrict__ Al,
    const __nv_bfloat16* __restrict__ Bh, const __nv_bfloat16* __restrict__ Bl,
    float* __restrict__ C) {
    extern __shared__ char dsm[];
    const int tid = threadIdx.x;
    const int wid = tid >> 5;
    const int lane = tid & 31;
    const int wm = wid & 1;        // 2 warp rows  (64 M each)
    const int wn = wid >> 1;       // 4 warp cols  (32 N each)
    const int m0 = blockIdx.y * GM;
    const int n0 = blockIdx.x * GN;

    uint32_t sb = (smem_u32(dsm) + 1023) & ~1023u;  // 1024-aligned tile base

    // per-thread ldmatrix raw offsets + swizzle masks (mask = (row&7)<<4, const/thread)
    const uint32_t aRow = (uint32_t)(wm * 64 + (lane & 15));
    const uint32_t aRaw = aRow * 128 + (uint32_t)(lane >> 4) * 16;
    const uint32_t aMsk = (aRow & 7) << 4;
    const uint32_t bRow = (uint32_t)(wn * 32 + ((lane >> 4) << 3) + (lane & 7));
    const uint32_t bRaw = bRow * 128 + (uint32_t)((lane >> 3) & 1) * 16;
    const uint32_t bMsk = (bRow & 7) << 4;

    float acc[4][4][4];
#pragma unroll
    for (int mi = 0; mi < 4; mi++)
#pragma unroll
        for (int ni = 0; ni < 4; ni++)
#pragma unroll
            for (int j = 0; j < 4; j++) acc[mi][ni][j] = 0.f;

    load_stage(sb, Ah, Al, Bh, Bl, m0, n0, 0, tid);
    load_stage(sb, Ah, Al, Bh, Bl, m0, n0, 1, tid);

    for (int s = 0; s < GNS; s++) {
        const uint32_t ab = sb + (uint32_t)(s & 1) * BUF_BYTES;
        if (s < GNS - 1) asm volatile("cp.async.wait_group 1;" ::: "memory");
        else             asm volatile("cp.async.wait_group 0;" ::: "memory");
        __syncthreads();

#pragma unroll
        for (int kk = 0; kk < 4; kk++) {
            const uint32_t kb = (uint32_t)(kk * 32);  // 16 bf16 per kstep
            uint32_t ah[4][4], al[4][4], bh[4][2], bl[4][2];
#pragma unroll
            for (int mi = 0; mi < 4; mi++) {
                uint32_t raw = aRaw + (uint32_t)(mi * 2048) + kb;
                ldsm4(ah[mi][0], ah[mi][1], ah[mi][2], ah[mi][3],
                      ab + (raw ^ aMsk));
                ldsm4(al[mi][0], al[mi][1], al[mi][2], al[mi][3],
                      ab + TILE_BYTES + (raw ^ aMsk));
            }
#pragma unroll
            for (int np = 0; np < 2; np++) {  // each x4 covers two n8 tiles
                uint32_t raw = bRaw + (uint32_t)(np * 2048) + kb;
                ldsm4(bh[np * 2][0], bh[np * 2][1], bh[np * 2 + 1][0],
                      bh[np * 2 + 1][1], ab + 2 * TILE_BYTES + (raw ^ bMsk));
                ldsm4(bl[np * 2][0], bl[np * 2][1], bl[np * 2 + 1][0],
                      bl[np * 2 + 1][1], ab + 3 * TILE_BYTES + (raw ^ bMsk));
            }
#pragma unroll
            for (int mi = 0; mi < 4; mi++)
#pragma unroll
                for (int ni = 0; ni < 4; ni++) {
                    mma16816(acc[mi][ni], ah[mi][0], ah[mi][1], ah[mi][2],
                             ah[mi][3], bh[ni][0], bh[ni][1]);
                    mma16816(acc[mi][ni], ah[mi][0], ah[mi][1], ah[mi][2],
                             ah[mi][3], bl[ni][0], bl[ni][1]);
                    mma16816(acc[mi][ni], al[mi][0], al[mi][1], al[mi][2],
                             al[mi][3], bh[ni][0], bh[ni][1]);
                }
        }
        __syncthreads();
        if (s + 2 < GNS)
            load_stage(sb, Ah, Al, Bh, Bl, m0, n0, s + 2, tid);
    }

    // epilogue: write fp32 accumulators
    const int rq = lane >> 2;
    const int cq = (lane & 3) * 2;
#pragma unroll
    for (int mi = 0; mi < 4; mi++) {
        int mrow = m0 + wm * 64 + mi * 16 + rq;
#pragma unroll
        for (int ni = 0; ni < 4; ni++) {
            float* p0 = C + (long)mrow * CC + n0 + wn * 32 + ni * 8 + cq;
            float* p1 = p0 + 8L * CC;
            *reinterpret_cast<float2*>(p0) = make_float2(acc[mi][ni][0], acc[mi][ni][1]);
            *reinterpret_cast<float2*>(p1) = make_float2(acc[mi][ni][2], acc[mi][ni][3]);
        }
    }
}

// ---------------- epilogue: ek, ekv, sigmoid(r), in place ----------------
__global__ void post_kernel(int n4) {
    int i = blockIdx.x * blockDim.x + threadIdx.x;
    if (i >= n4) return;
    float4 k4 = reinterpret_cast<float4*>(g_k)[i];
    float4 v4 = reinterpret_cast<float4*>(g_v)[i];
    float4 r4 = reinterpret_cast<float4*>(g_r)[i];
    float e;
    e = expf(k4.x); k4.x = e; v4.x *= e;
    e = expf(k4.y); k4.y = e; v4.y *= e;
    e = expf(k4.z); k4.z = e; v4.z *= e;
    e = expf(k4.w); k4.w = e; v4.w *= e;
    r4.x = 1.f / (1.f + expf(-r4.x));
    r4.y = 1.f / (1.f + expf(-r4.y));
    r4.z = 1.f / (1.f + expf(-r4.z));
    r4.w = 1.f / (1.f + expf(-r4.w));
    reinterpret_cast<float4*>(g_k)[i] = k4;
    reinterpret_cast<float4*>(g_v)[i] = v4;
    reinterpret_cast<float4*>(g_r)[i] = r4;
}

// ---------------- chunked linear-recurrence scan ----------------
__global__ void scan1_kernel() {
    int c = blockIdx.y * blockDim.x + threadIdx.x;
    int ch = blockIdx.x;
    float w = g_ew[c];
    float P = 0.f, Q = 0.f;
    int idx = ch * CHUNK * CC + c;
#pragma unroll 8
    for (int i = 0; i < CHUNK; i++) {
        P = fmaf(w, P, g_v[idx]);
        Q = fmaf(w, Q, g_k[idx]);
        idx += CC;
    }
    g_pp[ch * CC + c] = P;
    g_pq[ch * CC + c] = Q;
}

__global__ void scan2_kernel() {
    int c = blockIdx.x * blockDim.x + threadIdx.x;
    float wl = g_ewL[c];
    float P = 0.f, Q = 0.f;
#pragma unroll
    for (int j = 0; j < NCHUNK; j++) {
        g_ip[j * CC + c] = P;
        g_iq[j * CC + c] = Q;
        P = fmaf(wl, P, g_pp[j * CC + c]);
        Q = fmaf(wl, Q, g_pq[j * CC + c]);
    }
}

__global__ void scan3_kernel() {
    int c = blockIdx.y * blockDim.x + threadIdx.x;
    int ch = blockIdx.x;
    float w = g_ew[c], eu = g_eu[c];
    float P = g_ip[ch * CC + c], Q = g_iq[ch * CC + c];
    int idx = ch * CHUNK * CC + c;
#pragma unroll 4
    for (int i = 0; i < CHUNK; i++) {
        float ek = g_k[idx];
        float ekv = g_v[idx];
        float num = fmaf(eu, ekv, P);
        float den = fmaf(eu, ek, Q);
        float y = g_r[idx] * __fdividef(num, den);
        __nv_bfloat16 h = __float2bfloat16(y);
        g_a2h[idx] = h;
        g_a2l[idx] = __float2bfloat16(y - __bfloat162float(h));
        P = fmaf(w, P, ekv);
        Q = fmaf(w, Q, ek);
        idx += CC;
    }
}

// ---------------- launch ----------------
extern "C" void kernel_launch(void* const* d_in, const int* in_sizes, int n_in,
                              void* d_out, int out_size) {
    const float* x   = (const float*)d_in[0];
    const float* tf  = (const float*)d_in[1];
    const float* td  = (const float*)d_in[2];
    const float* tmk = (const float*)d_in[3];
    const float* tmv = (const float*)d_in[4];
    const float* tmr = (const float*)d_in[5];
    const float* Wk  = (const float*)d_in[6];
    const float* Wv  = (const float*)d_in[7];
    const float* Wr  = (const float*)d_in[8];
    const float* Wo  = (const float*)d_in[9];
    float* out = (float*)d_out;

    float *pk, *pv, *pr;
    cudaGetSymbolAddress((void**)&pk, g_k);
    cudaGetSymbolAddress((void**)&pv, g_v);
    cudaGetSymbolAddress((void**)&pr, g_r);
    __nv_bfloat16 *akh, *akl, *avh, *avl, *arh, *arl, *a2h, *a2l;
    __nv_bfloat16 *wkh, *wkl, *wvh, *wvl, *wrh, *wrl, *woh, *wol;
    cudaGetSymbolAddress((void**)&akh, g_akh); cudaGetSymbolAddress((void**)&akl, g_akl);
    cudaGetSymbolAddress((void**)&avh, g_avh); cudaGetSymbolAddress((void**)&avl, g_avl);
    cudaGetSymbolAddress((void**)&arh, g_arh); cudaGetSymbolAddress((void**)&arl, g_arl);
    cudaGetSymbolAddress((void**)&a2h, g_a2h); cudaGetSymbolAddress((void**)&a2l, g_a2l);
    cudaGetSymbolAddress((void**)&wkh, g_wkh); cudaGetSymbolAddress((void**)&wkl, g_wkl);
    cudaGetSymbolAddress((void**)&wvh, g_wvh); cudaGetSymbolAddress((void**)&wvl, g_wvl);
    cudaGetSymbolAddress((void**)&wrh, g_wrh); cudaGetSymbolAddress((void**)&wrl, g_wrl);
    cudaGetSymbolAddress((void**)&woh, g_woh); cudaGetSymbolAddress((void**)&wol, g_wol);

    cudaFuncSetAttribute(tc_gemm_kernel,
                         cudaFuncAttributeMaxDynamicSharedMemorySize, SMEM_DYN);

    precompute_kernel<<<(CC + 255) / 256, 256>>>(tf, td);

    dim3 wg(CC / 32, CC / 32);
    wsplit_kernel<<<wg, dim3(32, 8)>>>(Wk, wkh, wkl);
    wsplit_kernel<<<wg, dim3(32, 8)>>>(Wv, wvh, wvl);
    wsplit_kernel<<<wg, dim3(32, 8)>>>(Wr, wrh, wrl);
    wsplit_kernel<<<wg, dim3(32, 8)>>>(Wo, woh, wol);

    asplit_kernel<<<(TT * CC + 255) / 256, 256>>>(x, tmk, tmv, tmr);

    dim3 gg(CC / GN, TT / GM);
    tc_gemm_kernel<<<gg, 256, SMEM_DYN>>>(akh, akl, wkh, wkl, pk);
    tc_gemm_kernel<<<gg, 256, SMEM_DYN>>>(avh, avl, wvh, wvl, pv);
    tc_gemm_kernel<<<gg, 256, SMEM_DYN>>>(arh, arl, wrh, wrl, pr);

    post_kernel<<<(TT * CC / 4 + 255) / 256, 256>>>(TT * CC / 4);

    scan1_kernel<<<dim3(NCHUNK, CC / 256), 256>>>();
    scan2_kernel<<<CC / 256, 256>>>();
    scan3_kernel<<<dim3(NCHUNK, CC / 256), 256>>>();

    tc_gemm_kernel<<<gg, 256, SMEM_DYN>>>(a2h, a2l, woh, wol, out);
}

// round 11
// speedup vs baseline: 4.7170x; 1.3902x over previous
#include <cuda_runtime.h>
#include <cuda_fp16.h>
#include <math.h>
#include <stdint.h>

// Problem constants (T=4096, NE=DA=2048)
#define TT 4096
#define CC 2048
#define CHUNK 64
#define NCHUNK (TT / CHUNK)

// ---------------- scratch (no cudaMalloc allowed) ----------------
__device__ float g_k[TT * CC];    // exp(k)
__device__ float g_v[TT * CC];    // exp(k)*v
__device__ float g_r[TT * CC];    // sigmoid(r)
// fp16 hi/lo splits of the three mixed activations [T, CC] (K-major)
__device__ __half g_akh[TT * CC], g_akl[TT * CC];
__device__ __half g_avh[TT * CC], g_avl[TT * CC];
__device__ __half g_arh[TT * CC], g_arl[TT * CC];
// fp16 hi/lo split of sr*wkv [T, CC]
__device__ __half g_a2h[TT * CC], g_a2l[TT * CC];
// transposed weights [N, K] fp16 (K-major rows)
__device__ __half g_wk[CC * CC];
__device__ __half g_wv[CC * CC];
__device__ __half g_wr[CC * CC];
__device__ __half g_wo[CC * CC];
// scan partials
__device__ float g_pp[NCHUNK * CC];
__device__ float g_pq[NCHUNK * CC];
__device__ float g_ip[NCHUNK * CC];
__device__ float g_iq[NCHUNK * CC];
__device__ float g_ew[CC];
__device__ float g_ewL[CC];
__device__ float g_eu[CC];

// ---------------- per-channel constants ----------------
__global__ void precompute_kernel(const float* __restrict__ tf,
                                  const float* __restrict__ td) {
    int c = blockIdx.x * blockDim.x + threadIdx.x;
    if (c < CC) {
        float w = expf(-expf(td[c]));   // e^w, decay factor per step
        g_ew[c] = w;
        float p = w;
#pragma unroll
        for (int i = 0; i < 6; i++) p = p * p;   // w^64
        g_ewL[c] = p;
        g_eu[c] = expf(tf[c]);
    }
}

// ---------------- weight transpose: W[K,N] -> fp16 [N,K] ----------------
__global__ void wsplit_kernel(const float* __restrict__ W,
                              __half* __restrict__ H) {
    __shared__ float tile[32][33];
    int n0 = blockIdx.x * 32, k0 = blockIdx.y * 32;
    int tx = threadIdx.x, ty = threadIdx.y;  // 32 x 8
#pragma unroll
    for (int i = 0; i < 32; i += 8)
        tile[ty + i][tx] = W[(long)(k0 + ty + i) * CC + n0 + tx];
    __syncthreads();
#pragma unroll
    for (int i = 0; i < 32; i += 8) {
        float v = tile[tx][ty + i];  // = W[k0+tx][n0+ty+i]
        H[(long)(n0 + ty + i) * CC + k0 + tx] = __float2half_rn(v);
    }
}

// ---------------- activation mix + fp16 split ----------------
__global__ void asplit_kernel(const float* __restrict__ x,
                              const float* __restrict__ tmk,
                              const float* __restrict__ tmv,
                              const float* __restrict__ tmr) {
    int i = blockIdx.x * blockDim.x + threadIdx.x;
    if (i >= TT * CC) return;
    int c = i & (CC - 1);
    float xv = x[i];
    float xx = (i >= CC) ? x[i - CC] : 0.f;
    float d = xv - xx;
    float mk = fmaf(tmk[c], d, xx);
    float mv = fmaf(tmv[c], d, xx);
    float mr = fmaf(tmr[c], d, xx);
    __half h;
    h = __float2half_rn(mk); g_akh[i] = h; g_akl[i] = __float2half_rn(mk - __half2float(h));
    h = __float2half_rn(mv); g_avh[i] = h; g_avl[i] = __float2half_rn(mv - __half2float(h));
    h = __float2half_rn(mr); g_arh[i] = h; g_arl[i] = __float2half_rn(mr - __half2float(h));
}

// ---------------- fp16 2-product split GEMM via mma.sync ----------------
// C[M,N](fp32) = (Ah+Al)[M,K] @ B[N,K]^T, B single fp16.
// MODE 0: store acc; 1: store exp(acc); 2: store acc*EK[idx]; 3: store sigmoid(acc)
#define GM 128
#define GN 128
#define GK 64
#define GNS (CC / GK)         // 32 K-stages
#define TILE_BYTES 16384      // 128 rows x 128B (fp16 x 64)
#define BUF_BYTES (3 * TILE_BYTES)
#define NBUF 4
#define SMEM_DYN (NBUF * BUF_BYTES + 1024)

__device__ __forceinline__ uint32_t smem_u32(const void* p) {
    uint32_t a;
    asm("{ .reg .u64 t; cvta.to.shared.u64 t, %1; cvt.u32.u64 %0, t; }"
        : "=r"(a) : "l"(p));
    return a;
}
__device__ __forceinline__ void cp16(uint32_t dst, const void* src) {
    asm volatile("cp.async.cg.shared.global [%0], [%1], 16;" :: "r"(dst), "l"(src) : "memory");
}
__device__ __forceinline__ void ldsm4(uint32_t& r0, uint32_t& r1, uint32_t& r2,
                                      uint32_t& r3, uint32_t addr) {
    asm volatile("ldmatrix.sync.aligned.m8n8.x4.shared.b16 {%0,%1,%2,%3}, [%4];"
                 : "=r"(r0), "=r"(r1), "=r"(r2), "=r"(r3) : "r"(addr));
}
__device__ __forceinline__ void mma16816(float* c, const uint32_t* a,
                                         uint32_t b0, uint32_t b1) {
    asm volatile(
        "mma.sync.aligned.m16n8k16.row.col.f32.f16.f16.f32 "
        "{%0,%1,%2,%3}, {%4,%5,%6,%7}, {%8,%9}, {%0,%1,%2,%3};"
        : "+f"(c[0]), "+f"(c[1]), "+f"(c[2]), "+f"(c[3])
        : "r"(a[0]), "r"(a[1]), "r"(a[2]), "r"(a[3]), "r"(b0), "r"(b1));
}

__device__ __forceinline__ void load_stage(
    uint32_t sb, const __half* Ah, const __half* Al, const __half* B,
    int m0, int n0, int s, int tid) {
    uint32_t base = sb + (uint32_t)(s & (NBUF - 1)) * BUF_BYTES;
    int k0 = s * GK;
#pragma unroll
    for (int i = 0; i < 4; i++) {
        int c = tid + i * 256;          // 0..1023 chunk id
        int row = c >> 3;
        int colb = (c & 7) * 16;        // byte offset within 128B row
        uint32_t off = (uint32_t)(row * 128 + colb);
        uint32_t sw = off ^ ((off >> 3) & 0x70);
        const char* pa = (const char*)(Ah + (long)(m0 + row) * CC + k0) + colb;
        const char* pl = (const char*)(Al + (long)(m0 + row) * CC + k0) + colb;
        const char* pb = (const char*)(B + (long)(n0 + row) * CC + k0) + colb;
        cp16(base + sw, pa);
        cp16(base + TILE_BYTES + sw, pl);
        cp16(base + 2 * TILE_BYTES + sw, pb);
    }
    asm volatile("cp.async.commit_group;" ::: "memory");
}

template <int MODE>
__global__ __launch_bounds__(256, 1) void tc_gemm_kernel(
    const __half* __restrict__ Ah, const __half* __restrict__ Al,
    const __half* __restrict__ B, float* __restrict__ C,
    const float* __restrict__ EK) {
    extern __shared__ char dsm[];
    const int tid = threadIdx.x;
    const int wid = tid >> 5;
    const int lane = tid & 31;
    const int wm = wid & 1;        // 2 warp rows  (64 M each)
    const int wn = wid >> 1;       // 4 warp cols  (32 N each)
    const int m0 = blockIdx.y * GM;
    const int n0 = blockIdx.x * GN;

    uint32_t sb = (smem_u32(dsm) + 1023) & ~1023u;  // 1024-aligned tile base

    // per-thread ldmatrix raw offsets + swizzle masks
    const uint32_t aRow = (uint32_t)(wm * 64 + (lane & 15));
    const uint32_t aRaw = aRow * 128 + (uint32_t)(lane >> 4) * 16;
    const uint32_t aMsk = (aRow & 7) << 4;
    const uint32_t bRow = (uint32_t)(wn * 32 + ((lane >> 4) << 3) + (lane & 7));
    const uint32_t bRaw = bRow * 128 + (uint32_t)((lane >> 3) & 1) * 16;
    const uint32_t bMsk = (bRow & 7) << 4;

    float acc[4][4][4];
#pragma unroll
    for (int mi = 0; mi < 4; mi++)
#pragma unroll
        for (int ni = 0; ni < 4; ni++)
#pragma unroll
            for (int j = 0; j < 4; j++) acc[mi][ni][j] = 0.f;

    load_stage(sb, Ah, Al, B, m0, n0, 0, tid);
    load_stage(sb, Ah, Al, B, m0, n0, 1, tid);
    load_stage(sb, Ah, Al, B, m0, n0, 2, tid);

    for (int s = 0; s < GNS; s++) {
        const uint32_t ab = sb + (uint32_t)(s & (NBUF - 1)) * BUF_BYTES;
        if (s < GNS - 2)       asm volatile("cp.async.wait_group 2;" ::: "memory");
        else if (s == GNS - 2) asm volatile("cp.async.wait_group 1;" ::: "memory");
        else                   asm volatile("cp.async.wait_group 0;" ::: "memory");
        __syncthreads();

#pragma unroll
        for (int kk = 0; kk < 4; kk++) {
            const uint32_t kb = (uint32_t)(kk * 32);  // 16 fp16 per kstep
            uint32_t ah[4][4], al[4][4], bh[4][2];
#pragma unroll
            for (int mi = 0; mi < 4; mi++) {
                uint32_t raw = aRaw + (uint32_t)(mi * 2048) + kb;
                ldsm4(ah[mi][0], ah[mi][1], ah[mi][2], ah[mi][3],
                      ab + (raw ^ aMsk));
                ldsm4(al[mi][0], al[mi][1], al[mi][2], al[mi][3],
                      ab + TILE_BYTES + (raw ^ aMsk));
            }
#pragma unroll
            for (int np = 0; np < 2; np++) {  // each x4 covers two n8 tiles
                uint32_t raw = bRaw + (uint32_t)(np * 2048) + kb;
                ldsm4(bh[np * 2][0], bh[np * 2][1], bh[np * 2 + 1][0],
                      bh[np * 2 + 1][1], ab + 2 * TILE_BYTES + (raw ^ bMsk));
            }
#pragma unroll
            for (int mi = 0; mi < 4; mi++)
#pragma unroll
                for (int ni = 0; ni < 4; ni++) {
                    mma16816(acc[mi][ni], ah[mi], bh[ni][0], bh[ni][1]);
                    mma16816(acc[mi][ni], al[mi], bh[ni][0], bh[ni][1]);
                }
        }
        if (s + 3 < GNS)
            load_stage(sb, Ah, Al, B, m0, n0, s + 3, tid);
    }

    // epilogue: transform + write fp32
    const int rq = lane >> 2;
    const int cq = (lane & 3) * 2;
#pragma unroll
    for (int mi = 0; mi < 4; mi++) {
        int mrow = m0 + wm * 64 + mi * 16 + rq;
#pragma unroll
        for (int ni = 0; ni < 4; ni++) {
            long o0 = (long)mrow * CC + n0 + wn * 32 + ni * 8 + cq;
            long o1 = o0 + 8L * CC;
            float2 r0 = make_float2(acc[mi][ni][0], acc[mi][ni][1]);
            float2 r1 = make_float2(acc[mi][ni][2], acc[mi][ni][3]);
            if (MODE == 1) {           // exp(k)
                r0.x = expf(r0.x); r0.y = expf(r0.y);
                r1.x = expf(r1.x); r1.y = expf(r1.y);
            } else if (MODE == 2) {    // exp(k)*v
                float2 e0 = *reinterpret_cast<const float2*>(EK + o0);
                float2 e1 = *reinterpret_cast<const float2*>(EK + o1);
                r0.x *= e0.x; r0.y *= e0.y;
                r1.x *= e1.x; r1.y *= e1.y;
            } else if (MODE == 3) {    // sigmoid(r)
                r0.x = 1.f / (1.f + expf(-r0.x));
                r0.y = 1.f / (1.f + expf(-r0.y));
                r1.x = 1.f / (1.f + expf(-r1.x));
                r1.y = 1.f / (1.f + expf(-r1.y));
            }
            *reinterpret_cast<float2*>(C + o0) = r0;
            *reinterpret_cast<float2*>(C + o1) = r1;
        }
    }
}

// ---------------- chunked linear-recurrence scan ----------------
// g_k holds ek=exp(k), g_v holds ekv=exp(k)*v, g_r holds sr=sigmoid(r).
__global__ void scan1_kernel() {
    int c = blockIdx.y * blockDim.x + threadIdx.x;
    int ch = blockIdx.x;
    float w = g_ew[c];
    float P = 0.f, Q = 0.f;
    int idx = ch * CHUNK * CC + c;
#pragma unroll 8
    for (int i = 0; i < CHUNK; i++) {
        P = fmaf(w, P, g_v[idx]);
        Q = fmaf(w, Q, g_k[idx]);
        idx += CC;
    }
    g_pp[ch * CC + c] = P;
    g_pq[ch * CC + c] = Q;
}

__global__ void scan2_kernel() {
    int c = blockIdx.x * blockDim.x + threadIdx.x;
    float wl = g_ewL[c];
    float P = 0.f, Q = 0.f;
#pragma unroll
    for (int j = 0; j < NCHUNK; j++) {
        g_ip[j * CC + c] = P;
        g_iq[j * CC + c] = Q;
        P = fmaf(wl, P, g_pp[j * CC + c]);
        Q = fmaf(wl, Q, g_pq[j * CC + c]);
    }
}

__global__ void scan3_kernel() {
    int c = blockIdx.y * blockDim.x + threadIdx.x;
    int ch = blockIdx.x;
    float w = g_ew[c], eu = g_eu[c];
    float P = g_ip[ch * CC + c], Q = g_iq[ch * CC + c];
    int idx = ch * CHUNK * CC + c;
#pragma unroll 4
    for (int i = 0; i < CHUNK; i++) {
        float ek = g_k[idx];
        float ekv = g_v[idx];
        float num = fmaf(eu, ekv, P);
        float den = fmaf(eu, ek, Q);
        float y = g_r[idx] * __fdividef(num, den);
        __half h = __float2half_rn(y);
        g_a2h[idx] = h;
        g_a2l[idx] = __float2half_rn(y - __half2float(h));
        P = fmaf(w, P, ekv);
        Q = fmaf(w, Q, ek);
        idx += CC;
    }
}

// ---------------- launch ----------------
extern "C" void kernel_launch(void* const* d_in, const int* in_sizes, int n_in,
                              void* d_out, int out_size) {
    const float* x   = (const float*)d_in[0];
    const float* tf  = (const float*)d_in[1];
    const float* td  = (const float*)d_in[2];
    const float* tmk = (const float*)d_in[3];
    const float* tmv = (const float*)d_in[4];
    const float* tmr = (const float*)d_in[5];
    const float* Wk  = (const float*)d_in[6];
    const float* Wv  = (const float*)d_in[7];
    const float* Wr  = (const float*)d_in[8];
    const float* Wo  = (const float*)d_in[9];
    float* out = (float*)d_out;

    float *pk, *pv, *pr;
    cudaGetSymbolAddress((void**)&pk, g_k);
    cudaGetSymbolAddress((void**)&pv, g_v);
    cudaGetSymbolAddress((void**)&pr, g_r);
    __half *akh, *akl, *avh, *avl, *arh, *arl, *a2h, *a2l;
    __half *wk, *wv, *wr, *wo;
    cudaGetSymbolAddress((void**)&akh, g_akh); cudaGetSymbolAddress((void**)&akl, g_akl);
    cudaGetSymbolAddress((void**)&avh, g_avh); cudaGetSymbolAddress((void**)&avl, g_avl);
    cudaGetSymbolAddress((void**)&arh, g_arh); cudaGetSymbolAddress((void**)&arl, g_arl);
    cudaGetSymbolAddress((void**)&a2h, g_a2h); cudaGetSymbolAddress((void**)&a2l, g_a2l);
    cudaGetSymbolAddress((void**)&wk, g_wk); cudaGetSymbolAddress((void**)&wv, g_wv);
    cudaGetSymbolAddress((void**)&wr, g_wr); cudaGetSymbolAddress((void**)&wo, g_wo);

    cudaFuncSetAttribute(tc_gemm_kernel<0>,
                         cudaFuncAttributeMaxDynamicSharedMemorySize, SMEM_DYN);
    cudaFuncSetAttribute(tc_gemm_kernel<1>,
                         cudaFuncAttributeMaxDynamicSharedMemorySize, SMEM_DYN);
    cudaFuncSetAttribute(tc_gemm_kernel<2>,
                         cudaFuncAttributeMaxDynamicSharedMemorySize, SMEM_DYN);
    cudaFuncSetAttribute(tc_gemm_kernel<3>,
                         cudaFuncAttributeMaxDynamicSharedMemorySize, SMEM_DYN);

    precompute_kernel<<<(CC + 255) / 256, 256>>>(tf, td);

    dim3 wg(CC / 32, CC / 32);
    wsplit_kernel<<<wg, dim3(32, 8)>>>(Wk, wk);
    wsplit_kernel<<<wg, dim3(32, 8)>>>(Wv, wv);
    wsplit_kernel<<<wg, dim3(32, 8)>>>(Wr, wr);
    wsplit_kernel<<<wg, dim3(32, 8)>>>(Wo, wo);

    asplit_kernel<<<(TT * CC + 255) / 256, 256>>>(x, tmk, tmv, tmr);

    dim3 gg(CC / GN, TT / GM);
    tc_gemm_kernel<1><<<gg, 256, SMEM_DYN>>>(akh, akl, wk, pk, nullptr);
    tc_gemm_kernel<2><<<gg, 256, SMEM_DYN>>>(avh, avl, wv, pv, pk);
    tc_gemm_kernel<3><<<gg, 256, SMEM_DYN>>>(arh, arl, wr, pr, nullptr);

    scan1_kernel<<<dim3(NCHUNK, CC / 256), 256>>>();
    scan2_kernel<<<CC / 256, 256>>>();
    scan3_kernel<<<dim3(NCHUNK, CC / 256), 256>>>();

    tc_gemm_kernel<0><<<gg, 256, SMEM_DYN>>>(a2h, a2l, wo, out, nullptr);
}

// round 12
// speedup vs baseline: 7.2198x; 1.5306x over previous
#include <cuda_runtime.h>
#include <cuda_fp16.h>
#include <math.h>
#include <stdint.h>

// Problem constants (T=4096, NE=DA=2048)
#define TT 4096
#define CC 2048
#define CHUNK 64
#define NCHUNK (TT / CHUNK)

// ---------------- scratch (no cudaMalloc allowed) ----------------
__device__ float g_k[TT * CC];    // exp(k)
__device__ float g_v[TT * CC];    // exp(k)*v
__device__ float g_r[TT * CC];    // sigmoid(r)
// fp16 mixed activations [T, CC] (K-major)
__device__ __half g_ak[TT * CC];
__device__ __half g_av[TT * CC];
__device__ __half g_ar[TT * CC];
// fp16 sr*wkv [T, CC]
__device__ __half g_a2[TT * CC];
// transposed weights [N, K] fp16 (K-major rows)
__device__ __half g_wk[CC * CC];
__device__ __half g_wv[CC * CC];
__device__ __half g_wr[CC * CC];
__device__ __half g_wo[CC * CC];
// scan partials
__device__ float g_pp[NCHUNK * CC];
__device__ float g_pq[NCHUNK * CC];
__device__ float g_ip[NCHUNK * CC];
__device__ float g_iq[NCHUNK * CC];
__device__ float g_ew[CC];
__device__ float g_ewL[CC];
__device__ float g_eu[CC];

// ---------------- per-channel constants ----------------
__global__ void precompute_kernel(const float* __restrict__ tf,
                                  const float* __restrict__ td) {
    int c = blockIdx.x * blockDim.x + threadIdx.x;
    if (c < CC) {
        float w = expf(-expf(td[c]));   // e^w, decay factor per step
        g_ew[c] = w;
        float p = w;
#pragma unroll
        for (int i = 0; i < 6; i++) p = p * p;   // w^64
        g_ewL[c] = p;
        g_eu[c] = expf(tf[c]);
    }
}

// ---------------- weight transpose: W[K,N] -> fp16 [N,K], 4 weights ----------------
__global__ void wsplit4_kernel(const float* __restrict__ W0,
                               const float* __restrict__ W1,
                               const float* __restrict__ W2,
                               const float* __restrict__ W3) {
    __shared__ float tile[32][33];
    const float* W = (blockIdx.z == 0) ? W0 : (blockIdx.z == 1) ? W1
                   : (blockIdx.z == 2) ? W2 : W3;
    __half* H;
    {
        __half* h0; __half* h1; __half* h2; __half* h3;
        // device-side symbol addresses resolve statically
        h0 = g_wk; h1 = g_wv; h2 = g_wr; h3 = g_wo;
        H = (blockIdx.z == 0) ? h0 : (blockIdx.z == 1) ? h1
          : (blockIdx.z == 2) ? h2 : h3;
    }
    int n0 = blockIdx.x * 32, k0 = blockIdx.y * 32;
    int tx = threadIdx.x, ty = threadIdx.y;  // 32 x 8
#pragma unroll
    for (int i = 0; i < 32; i += 8)
        tile[ty + i][tx] = W[(long)(k0 + ty + i) * CC + n0 + tx];
    __syncthreads();
#pragma unroll
    for (int i = 0; i < 32; i += 8) {
        float v = tile[tx][ty + i];  // = W[k0+tx][n0+ty+i]
        H[(long)(n0 + ty + i) * CC + k0 + tx] = __float2half_rn(v);
    }
}

// ---------------- activation mix -> fp16 ----------------
__global__ void asplit_kernel(const float* __restrict__ x,
                              const float* __restrict__ tmk,
                              const float* __restrict__ tmv,
                              const float* __restrict__ tmr) {
    int i = blockIdx.x * blockDim.x + threadIdx.x;
    if (i >= TT * CC) return;
    int c = i & (CC - 1);
    float xv = x[i];
    float xx = (i >= CC) ? x[i - CC] : 0.f;
    float d = xv - xx;
    g_ak[i] = __float2half_rn(fmaf(tmk[c], d, xx));
    g_av[i] = __float2half_rn(fmaf(tmv[c], d, xx));
    g_ar[i] = __float2half_rn(fmaf(tmr[c], d, xx));
}

// ---------------- fp16 single-product GEMM via mma.sync ----------------
// C[M,N](fp32) = A[M,K] @ B[N,K]^T, fp16 operands, fp32 accum.
// MODE 0: store acc; 1: store exp(acc); 2: store acc*EK[idx]; 3: store sigmoid(acc)
#define GM 128
#define GN 128
#define GK 64
#define GNS (CC / GK)         // 32 K-stages
#define TILE_BYTES 16384      // 128 rows x 128B (fp16 x 64)
#define BUF_BYTES (2 * TILE_BYTES)
#define NBUF 4
#define SMEM_DYN (NBUF * BUF_BYTES + 1024)

__device__ __forceinline__ uint32_t smem_u32(const void* p) {
    uint32_t a;
    asm("{ .reg .u64 t; cvta.to.shared.u64 t, %1; cvt.u32.u64 %0, t; }"
        : "=r"(a) : "l"(p));
    return a;
}
__device__ __forceinline__ void cp16(uint32_t dst, const void* src) {
    asm volatile("cp.async.cg.shared.global [%0], [%1], 16;" :: "r"(dst), "l"(src) : "memory");
}
__device__ __forceinline__ void ldsm4(uint32_t& r0, uint32_t& r1, uint32_t& r2,
                                      uint32_t& r3, uint32_t addr) {
    asm volatile("ldmatrix.sync.aligned.m8n8.x4.shared.b16 {%0,%1,%2,%3}, [%4];"
                 : "=r"(r0), "=r"(r1), "=r"(r2), "=r"(r3) : "r"(addr));
}
__device__ __forceinline__ void mma16816(float* c, const uint32_t* a,
                                         uint32_t b0, uint32_t b1) {
    asm volatile(
        "mma.sync.aligned.m16n8k16.row.col.f32.f16.f16.f32 "
        "{%0,%1,%2,%3}, {%4,%5,%6,%7}, {%8,%9}, {%0,%1,%2,%3};"
        : "+f"(c[0]), "+f"(c[1]), "+f"(c[2]), "+f"(c[3])
        : "r"(a[0]), "r"(a[1]), "r"(a[2]), "r"(a[3]), "r"(b0), "r"(b1));
}

__device__ __forceinline__ void load_stage(
    uint32_t sb, const __half* A, const __half* B,
    int m0, int n0, int s, int tid) {
    uint32_t base = sb + (uint32_t)(s & (NBUF - 1)) * BUF_BYTES;
    int k0 = s * GK;
#pragma unroll
    for (int i = 0; i < 4; i++) {
        int c = tid + i * 256;          // 0..1023 chunk id
        int row = c >> 3;
        int colb = (c & 7) * 16;        // byte offset within 128B row
        uint32_t off = (uint32_t)(row * 128 + colb);
        uint32_t sw = off ^ ((off >> 3) & 0x70);
        const char* pa = (const char*)(A + (long)(m0 + row) * CC + k0) + colb;
        const char* pb = (const char*)(B + (long)(n0 + row) * CC + k0) + colb;
        cp16(base + sw, pa);
        cp16(base + TILE_BYTES + sw, pb);
    }
    asm volatile("cp.async.commit_group;" ::: "memory");
}

template <int MODE>
__global__ __launch_bounds__(256, 1) void tc_gemm_kernel(
    const __half* __restrict__ A, const __half* __restrict__ B,
    float* __restrict__ C, const float* __restrict__ EK) {
    extern __shared__ char dsm[];
    const int tid = threadIdx.x;
    const int wid = tid >> 5;
    const int lane = tid & 31;
    const int wm = wid & 1;        // 2 warp rows  (64 M each)
    const int wn = wid >> 1;       // 4 warp cols  (32 N each)
    const int m0 = blockIdx.y * GM;
    const int n0 = blockIdx.x * GN;

    uint32_t sb = (smem_u32(dsm) + 1023) & ~1023u;  // 1024-aligned tile base

    // per-thread ldmatrix raw offsets + swizzle masks
    const uint32_t aRow = (uint32_t)(wm * 64 + (lane & 15));
    const uint32_t aRaw = aRow * 128 + (uint32_t)(lane >> 4) * 16;
    const uint32_t aMsk = (aRow & 7) << 4;
    const uint32_t bRow = (uint32_t)(wn * 32 + ((lane >> 4) << 3) + (lane & 7));
    const uint32_t bRaw = bRow * 128 + (uint32_t)((lane >> 3) & 1) * 16;
    const uint32_t bMsk = (bRow & 7) << 4;

    float acc[4][4][4];
#pragma unroll
    for (int mi = 0; mi < 4; mi++)
#pragma unroll
        for (int ni = 0; ni < 4; ni++)
#pragma unroll
            for (int j = 0; j < 4; j++) acc[mi][ni][j] = 0.f;

    load_stage(sb, A, B, m0, n0, 0, tid);
    load_stage(sb, A, B, m0, n0, 1, tid);
    load_stage(sb, A, B, m0, n0, 2, tid);

    for (int s = 0; s < GNS; s++) {
        const uint32_t ab = sb + (uint32_t)(s & (NBUF - 1)) * BUF_BYTES;
        if (s < GNS - 2)       asm volatile("cp.async.wait_group 2;" ::: "memory");
        else if (s == GNS - 2) asm volatile("cp.async.wait_group 1;" ::: "memory");
        else                   asm volatile("cp.async.wait_group 0;" ::: "memory");
        __syncthreads();

#pragma unroll
        for (int kk = 0; kk < 4; kk++) {
            const uint32_t kb = (uint32_t)(kk * 32);  // 16 fp16 per kstep
            uint32_t ah[4][4], bh[4][2];
#pragma unroll
            for (int mi = 0; mi < 4; mi++) {
                uint32_t raw = aRaw + (uint32_t)(mi * 2048) + kb;
                ldsm4(ah[mi][0], ah[mi][1], ah[mi][2], ah[mi][3],
                      ab + (raw ^ aMsk));
            }
#pragma unroll
            for (int np = 0; np < 2; np++) {  // each x4 covers two n8 tiles
                uint32_t raw = bRaw + (uint32_t)(np * 2048) + kb;
                ldsm4(bh[np * 2][0], bh[np * 2][1], bh[np * 2 + 1][0],
                      bh[np * 2 + 1][1], ab + TILE_BYTES + (raw ^ bMsk));
            }
#pragma unroll
            for (int mi = 0; mi < 4; mi++)
#pragma unroll
                for (int ni = 0; ni < 4; ni++)
                    mma16816(acc[mi][ni], ah[mi], bh[ni][0], bh[ni][1]);
        }
        if (s + 3 < GNS)
            load_stage(sb, A, B, m0, n0, s + 3, tid);
    }

    // epilogue: transform + write fp32
    const int rq = lane >> 2;
    const int cq = (lane & 3) * 2;
#pragma unroll
    for (int mi = 0; mi < 4; mi++) {
        int mrow = m0 + wm * 64 + mi * 16 + rq;
#pragma unroll
        for (int ni = 0; ni < 4; ni++) {
            long o0 = (long)mrow * CC + n0 + wn * 32 + ni * 8 + cq;
            long o1 = o0 + 8L * CC;
            float2 r0 = make_float2(acc[mi][ni][0], acc[mi][ni][1]);
            float2 r1 = make_float2(acc[mi][ni][2], acc[mi][ni][3]);
            if (MODE == 1) {           // exp(k)
                r0.x = expf(r0.x); r0.y = expf(r0.y);
                r1.x = expf(r1.x); r1.y = expf(r1.y);
            } else if (MODE == 2) {    // exp(k)*v
                float2 e0 = *reinterpret_cast<const float2*>(EK + o0);
                float2 e1 = *reinterpret_cast<const float2*>(EK + o1);
                r0.x *= e0.x; r0.y *= e0.y;
                r1.x *= e1.x; r1.y *= e1.y;
            } else if (MODE == 3) {    // sigmoid(r)
                r0.x = 1.f / (1.f + expf(-r0.x));
                r0.y = 1.f / (1.f + expf(-r0.y));
                r1.x = 1.f / (1.f + expf(-r1.x));
                r1.y = 1.f / (1.f + expf(-r1.y));
            }
            *reinterpret_cast<float2*>(C + o0) = r0;
            *reinterpret_cast<float2*>(C + o1) = r1;
        }
    }
}

// ---------------- chunked linear-recurrence scan ----------------
// g_k holds ek=exp(k), g_v holds ekv=exp(k)*v, g_r holds sr=sigmoid(r).
__global__ void scan1_kernel() {
    int c = blockIdx.y * blockDim.x + threadIdx.x;
    int ch = blockIdx.x;
    float w = g_ew[c];
    float P = 0.f, Q = 0.f;
    int idx = ch * CHUNK * CC + c;
#pragma unroll 8
    for (int i = 0; i < CHUNK; i++) {
        P = fmaf(w, P, g_v[idx]);
        Q = fmaf(w, Q, g_k[idx]);
        idx += CC;
    }
    g_pp[ch * CC + c] = P;
    g_pq[ch * CC + c] = Q;
}

__global__ void scan2_kernel() {
    int c = blockIdx.x * blockDim.x + threadIdx.x;
    float wl = g_ewL[c];
    float P = 0.f, Q = 0.f;
#pragma unroll
    for (int j = 0; j < NCHUNK; j++) {
        g_ip[j * CC + c] = P;
        g_iq[j * CC + c] = Q;
        P = fmaf(wl, P, g_pp[j * CC + c]);
        Q = fmaf(wl, Q, g_pq[j * CC + c]);
    }
}

__global__ void scan3_kernel() {
    int c = blockIdx.y * blockDim.x + threadIdx.x;
    int ch = blockIdx.x;
    float w = g_ew[c], eu = g_eu[c];
    float P = g_ip[ch * CC + c], Q = g_iq[ch * CC + c];
    int idx = ch * CHUNK * CC + c;
#pragma unroll 4
    for (int i = 0; i < CHUNK; i++) {
        float ek = g_k[idx];
        float ekv = g_v[idx];
        float num = fmaf(eu, ekv, P);
        float den = fmaf(eu, ek, Q);
        float y = g_r[idx] * __fdividef(num, den);
        g_a2[idx] = __float2half_rn(y);
        P = fmaf(w, P, ekv);
        Q = fmaf(w, Q, ek);
        idx += CC;
    }
}

// ---------------- launch ----------------
extern "C" void kernel_launch(void* const* d_in, const int* in_sizes, int n_in,
                              void* d_out, int out_size) {
    const float* x   = (const float*)d_in[0];
    const float* tf  = (const float*)d_in[1];
    const float* td  = (const float*)d_in[2];
    const float* tmk = (const float*)d_in[3];
    const float* tmv = (const float*)d_in[4];
    const float* tmr = (const float*)d_in[5];
    const float* Wk  = (const float*)d_in[6];
    const float* Wv  = (const float*)d_in[7];
    const float* Wr  = (const float*)d_in[8];
    const float* Wo  = (const float*)d_in[9];
    float* out = (float*)d_out;

    float *pk, *pv, *pr;
    cudaGetSymbolAddress((void**)&pk, g_k);
    cudaGetSymbolAddress((void**)&pv, g_v);
    cudaGetSymbolAddress((void**)&pr, g_r);
    __half *ak, *av, *ar, *a2, *wk, *wv, *wr, *wo;
    cudaGetSymbolAddress((void**)&ak, g_ak);
    cudaGetSymbolAddress((void**)&av, g_av);
    cudaGetSymbolAddress((void**)&ar, g_ar);
    cudaGetSymbolAddress((void**)&a2, g_a2);
    cudaGetSymbolAddress((void**)&wk, g_wk);
    cudaGetSymbolAddress((void**)&wv, g_wv);
    cudaGetSymbolAddress((void**)&wr, g_wr);
    cudaGetSymbolAddress((void**)&wo, g_wo);

    cudaFuncSetAttribute(tc_gemm_kernel<0>,
                         cudaFuncAttributeMaxDynamicSharedMemorySize, SMEM_DYN);
    cudaFuncSetAttribute(tc_gemm_kernel<1>,
                         cudaFuncAttributeMaxDynamicSharedMemorySize, SMEM_DYN);
    cudaFuncSetAttribute(tc_gemm_kernel<2>,
                         cudaFuncAttributeMaxDynamicSharedMemorySize, SMEM_DYN);
    cudaFuncSetAttribute(tc_gemm_kernel<3>,
                         cudaFuncAttributeMaxDynamicSharedMemorySize, SMEM_DYN);

    precompute_kernel<<<(CC + 255) / 256, 256>>>(tf, td);

    wsplit4_kernel<<<dim3(CC / 32, CC / 32, 4), dim3(32, 8)>>>(Wk, Wv, Wr, Wo);

    asplit_kernel<<<(TT * CC + 255) / 256, 256>>>(x, tmk, tmv, tmr);

    dim3 gg(CC / GN, TT / GM);
    tc_gemm_kernel<1><<<gg, 256, SMEM_DYN>>>(ak, wk, pk, nullptr);
    tc_gemm_kernel<2><<<gg, 256, SMEM_DYN>>>(av, wv, pv, pk);
    tc_gemm_kernel<3><<<gg, 256, SMEM_DYN>>>(ar, wr, pr, nullptr);

    scan1_kernel<<<dim3(NCHUNK, CC / 256), 256>>>();
    scan2_kernel<<<CC / 256, 256>>>();
    scan3_kernel<<<dim3(NCHUNK, CC / 256), 256>>>();

    tc_gemm_kernel<0><<<gg, 256, SMEM_DYN>>>(a2, wo, out, nullptr);
}